// round 1
// baseline (speedup 1.0000x reference)
#include <cuda_runtime.h>
#include <math.h>

#define NTOK   4096      // B*S
#define HID    2048
#define NH     16
#define HD     128
#define MLPD   8192
#define SEQL   2048
#define NBATCH 2

// ------------------------- persistent device scratch -------------------------
__device__ float g_wq[HID * HID];
__device__ float g_wk[HID * HID];
__device__ float g_wv[HID * HID];
__device__ float g_wo[HID * HID];
__device__ float g_wg[MLPD * HID];
__device__ float g_wu[MLPD * HID];
__device__ float g_wd[HID * MLPD];
__device__ float g_sq[HID], g_sk[HID], g_sv[HID], g_so[HID];
__device__ float g_sg[MLPD], g_su[MLPD], g_sd[HID];

__device__ float g_aq[NTOK * MLPD];      // quantized activations (max K = 8192)
__device__ float g_as[NTOK];             // per-token activation scales
__device__ float g_qkv[3 * NTOK * HID];  // q_t, k_t, v_t in [T, H*D] layout
__device__ float g_q[NTOK * HID];        // roped q, [B,H,S,D]
__device__ float g_k[NTOK * HID];        // roped k, [B,H,S,D]
__device__ float g_attno[NTOK * HID];    // attention output, [T, H*D]
__device__ float g_x1[NTOK * HID];       // residual after attention
__device__ float g_gate[NTOK * MLPD];
__device__ float g_up[NTOK * MLPD];
__device__ float g_down[NTOK * HID];     // also reused for attn out-proj

// ------------------------- weight quantization -------------------------
// one block per output row: w_scale = mean|W| + 1e-8; Wq = clip(rint(W/w_scale),-1,1)
// rowscale = w_scale * alpha / 127
__global__ void quant_w_kernel(const float* __restrict__ W,
                               const float* __restrict__ alpha,
                               float* __restrict__ Wq,
                               float* __restrict__ rs, int K) {
    int o = blockIdx.x;
    const float* row = W + (size_t)o * K;
    __shared__ float red[256];
    float s = 0.f;
    for (int i = threadIdx.x; i < K; i += 256) s += fabsf(row[i]);
    red[threadIdx.x] = s;
    __syncthreads();
    for (int st = 128; st > 0; st >>= 1) {
        if (threadIdx.x < st) red[threadIdx.x] += red[threadIdx.x + st];
        __syncthreads();
    }
    float wsc = red[0] / (float)K + 1e-8f;
    if (threadIdx.x == 0) rs[o] = wsc * alpha[o] / 127.0f;
    float* orow = Wq + (size_t)o * K;
    for (int i = threadIdx.x; i < K; i += 256) {
        float v = rintf(row[i] / wsc);              // round, then clip (matches ref)
        orow[i] = fminf(fmaxf(v, -1.f), 1.f);
    }
}

// ------------------------- rmsnorm + activation quant (N = 2048) -------------------------
__global__ void rms_quant_kernel(const float* __restrict__ x,
                                 const float* __restrict__ w,
                                 float* __restrict__ aq,
                                 float* __restrict__ as_) {
    int t = blockIdx.x;
    const float* row = x + (size_t)t * HID;
    float v[8], h[8];
    float ss = 0.f;
#pragma unroll
    for (int j = 0; j < 8; j++) {
        v[j] = row[j * 256 + threadIdx.x];
        ss += v[j] * v[j];
    }
    __shared__ float red[256];
    red[threadIdx.x] = ss;
    __syncthreads();
    for (int st = 128; st > 0; st >>= 1) {
        if (threadIdx.x < st) red[threadIdx.x] += red[threadIdx.x + st];
        __syncthreads();
    }
    float rms = sqrtf(red[0] / (float)HID + 1e-6f);
    __syncthreads();
    float mx = 0.f;
#pragma unroll
    for (int j = 0; j < 8; j++) {
        h[j] = v[j] / rms * w[j * 256 + threadIdx.x];
        mx = fmaxf(mx, fabsf(h[j]));
    }
    red[threadIdx.x] = mx;
    __syncthreads();
    for (int st = 128; st > 0; st >>= 1) {
        if (threadIdx.x < st) red[threadIdx.x] = fmaxf(red[threadIdx.x], red[threadIdx.x + st]);
        __syncthreads();
    }
    float asc = red[0] + 1e-8f;
    if (threadIdx.x == 0) as_[t] = asc;
    float* orow = aq + (size_t)t * HID;
#pragma unroll
    for (int j = 0; j < 8; j++) {
        float q = h[j] / asc * 127.0f;
        q = fminf(fmaxf(q, -128.f), 127.f);         // clip, then round (matches ref)
        orow[j * 256 + threadIdx.x] = rintf(q);
    }
}

// ------------------------- plain activation quant (generic N) -------------------------
__global__ void act_quant_kernel(const float* __restrict__ x,
                                 float* __restrict__ aq,
                                 float* __restrict__ as_, int N) {
    int t = blockIdx.x;
    const float* row = x + (size_t)t * N;
    __shared__ float red[256];
    float mx = 0.f;
    for (int i = threadIdx.x; i < N; i += 256) mx = fmaxf(mx, fabsf(row[i]));
    red[threadIdx.x] = mx;
    __syncthreads();
    for (int st = 128; st > 0; st >>= 1) {
        if (threadIdx.x < st) red[threadIdx.x] = fmaxf(red[threadIdx.x], red[threadIdx.x + st]);
        __syncthreads();
    }
    float asc = red[0] + 1e-8f;
    if (threadIdx.x == 0) as_[t] = asc;
    float* orow = aq + (size_t)t * N;
    for (int i = threadIdx.x; i < N; i += 256) {
        float q = row[i] / asc * 127.0f;
        q = fminf(fmaxf(q, -128.f), 127.f);
        orow[i] = rintf(q);
    }
}

// ------------------------- fp32 GEMM: C[t,o] = sum_k A[t,k]*W[o,k], scaled -------------------------
// 128x128 tile, BK=16, 256 threads, 8x8 micro-tile
__global__ void __launch_bounds__(256)
gemm_bitlin_kernel(const float* __restrict__ A, const float* __restrict__ B,
                   const float* __restrict__ rs, const float* __restrict__ asc,
                   float* __restrict__ C, int K, int N) {
    __shared__ float As[16][128];
    __shared__ float Bs[16][128];
    const int tid = threadIdx.x;
    const int tx = tid & 15, ty = tid >> 4;
    const size_t rowBase = (size_t)blockIdx.y * 128;
    const size_t colBase = (size_t)blockIdx.x * 128;
    const float* Ab = A + rowBase * K;
    const float* Bb = B + colBase * K;
    float acc[8][8];
#pragma unroll
    for (int m = 0; m < 8; m++)
#pragma unroll
        for (int n = 0; n < 8; n++) acc[m][n] = 0.f;

    const int ar = tid >> 2;           // 0..63
    const int ac = (tid & 3) * 4;      // 0,4,8,12

    for (int k0 = 0; k0 < K; k0 += 16) {
        float4 a0 = *(const float4*)(Ab + (size_t)ar * K + k0 + ac);
        float4 a1 = *(const float4*)(Ab + (size_t)(ar + 64) * K + k0 + ac);
        float4 b0 = *(const float4*)(Bb + (size_t)ar * K + k0 + ac);
        float4 b1 = *(const float4*)(Bb + (size_t)(ar + 64) * K + k0 + ac);
        __syncthreads();
        As[ac + 0][ar] = a0.x; As[ac + 1][ar] = a0.y; As[ac + 2][ar] = a0.z; As[ac + 3][ar] = a0.w;
        As[ac + 0][ar + 64] = a1.x; As[ac + 1][ar + 64] = a1.y; As[ac + 2][ar + 64] = a1.z; As[ac + 3][ar + 64] = a1.w;
        Bs[ac + 0][ar] = b0.x; Bs[ac + 1][ar] = b0.y; Bs[ac + 2][ar] = b0.z; Bs[ac + 3][ar] = b0.w;
        Bs[ac + 0][ar + 64] = b1.x; Bs[ac + 1][ar + 64] = b1.y; Bs[ac + 2][ar + 64] = b1.z; Bs[ac + 3][ar + 64] = b1.w;
        __syncthreads();
#pragma unroll
        for (int kk = 0; kk < 16; kk++) {
            float4 av0 = *(const float4*)&As[kk][ty * 8];
            float4 av1 = *(const float4*)&As[kk][ty * 8 + 4];
            float4 bv0 = *(const float4*)&Bs[kk][tx * 8];
            float4 bv1 = *(const float4*)&Bs[kk][tx * 8 + 4];
            float arr[8] = {av0.x, av0.y, av0.z, av0.w, av1.x, av1.y, av1.z, av1.w};
            float brr[8] = {bv0.x, bv0.y, bv0.z, bv0.w, bv1.x, bv1.y, bv1.z, bv1.w};
#pragma unroll
            for (int m = 0; m < 8; m++)
#pragma unroll
                for (int n = 0; n < 8; n++) acc[m][n] += arr[m] * brr[n];
        }
    }
#pragma unroll
    for (int m = 0; m < 8; m++) {
        size_t t = rowBase + ty * 8 + m;
        float at = asc[t];
#pragma unroll
        for (int n = 0; n < 8; n++) {
            size_t o = colBase + tx * 8 + n;
            C[t * N + o] = acc[m][n] * rs[o] * at;
        }
    }
}

// ------------------------- RoPE + [T,H*D] -> [B,H,S,D] transpose for q,k -------------------------
__global__ void rope_kernel(const float* __restrict__ qt, const float* __restrict__ kt,
                            float* __restrict__ qo, float* __restrict__ ko) {
    int idx = blockIdx.x * blockDim.x + threadIdx.x;   // NTOK*NH*64 threads
    if (idx >= NTOK * NH * 64) return;
    int d = idx & 63;
    int th = idx >> 6;
    int h = th & (NH - 1);
    int t = th >> 4;
    int s = t & (SEQL - 1);
    int b = t >> 11;
    float invf = 1.0f / powf(10000.0f, (float)d / 64.0f);
    float ang = (float)s * invf;
    float sn, c;
    sincosf(ang, &sn, &c);
    size_t in0 = (size_t)t * HID + h * HD + d;
    size_t ob = ((size_t)(b * NH + h) * SEQL + s) * (size_t)HD + d;
    float x1 = qt[in0], x2 = qt[in0 + 64];
    qo[ob] = x1 * c - x2 * sn;
    qo[ob + 64] = x2 * c + x1 * sn;
    float y1 = kt[in0], y2 = kt[in0 + 64];
    ko[ob] = y1 * c - y2 * sn;
    ko[ob + 64] = y2 * c + y1 * sn;
}

// ------------------------- fused causal attention -------------------------
// 8 warps/block, warp w owns query row s_base+w; 32-key K/V tiles staged in smem.
__global__ void __launch_bounds__(256)
attn_kernel(const float* __restrict__ q, const float* __restrict__ k,
            const float* __restrict__ vt, const int* __restrict__ mask,
            float* __restrict__ out) {
    __shared__ float Ks[32 * HD];
    __shared__ float Vs[32 * HD];
    const int wid = threadIdx.x >> 5;
    const int lane = threadIdx.x & 31;
    const int R = blockIdx.x * 8;          // first global row of the block
    const int s_base = R & (SEQL - 1);
    const int bh = R >> 11;                // R / SEQL
    const int h = bh & (NH - 1);
    const int b = bh >> 4;
    const int s = s_base + wid;

    const float* qrow = q + ((size_t)bh * SEQL + s) * HD;
    float q0 = qrow[lane], q1 = qrow[lane + 32], q2 = qrow[lane + 64], q3 = qrow[lane + 96];
    const float* kb = k + (size_t)bh * SEQL * HD;
    const float* vb = vt + (size_t)b * SEQL * HID + (size_t)h * HD;
    const int* mrow = mask + b * SEQL;

    float m = -1e30f, l = 0.f, a0 = 0.f, a1 = 0.f, a2 = 0.f, a3 = 0.f;
    const float scale = 0.08838834764831845f;   // 1/sqrt(128)
    const int jmax = s_base + 8;                // keys needed by any row in block

    for (int j0 = 0; j0 < jmax; j0 += 32) {
        __syncthreads();
        int nk = min(32, jmax - j0);
        for (int i = threadIdx.x; i < nk * HD; i += 256) {
            Ks[i] = kb[(size_t)j0 * HD + i];
            int kj = i >> 7, d = i & 127;
            Vs[i] = vb[(size_t)(j0 + kj) * HID + d];
        }
        __syncthreads();
        int jend = min(nk, s - j0 + 1);
        for (int jj = 0; jj < jend; jj++) {
            const float* kr = Ks + jj * HD;
            float dot = q0 * kr[lane] + q1 * kr[lane + 32] + q2 * kr[lane + 64] + q3 * kr[lane + 96];
            dot += __shfl_xor_sync(0xffffffffu, dot, 16);
            dot += __shfl_xor_sync(0xffffffffu, dot, 8);
            dot += __shfl_xor_sync(0xffffffffu, dot, 4);
            dot += __shfl_xor_sync(0xffffffffu, dot, 2);
            dot += __shfl_xor_sync(0xffffffffu, dot, 1);
            float sc = dot * scale;
            sc = (mrow[j0 + jj] == 0) ? -10000.f : fmaxf(sc, -10000.f);
            float nm = fmaxf(m, sc);
            float cor = __expf(m - nm);
            float p = __expf(sc - nm);
            l = l * cor + p;
            const float* vr = Vs + jj * HD;
            a0 = a0 * cor + p * vr[lane];
            a1 = a1 * cor + p * vr[lane + 32];
            a2 = a2 * cor + p * vr[lane + 64];
            a3 = a3 * cor + p * vr[lane + 96];
            m = nm;
        }
    }
    float inv = 1.f / l;
    size_t ob = ((size_t)b * SEQL + s) * HID + (size_t)h * HD;
    out[ob + lane] = a0 * inv;
    out[ob + lane + 32] = a1 * inv;
    out[ob + lane + 64] = a2 * inv;
    out[ob + lane + 96] = a3 * inv;
}

// ------------------------- elementwise -------------------------
__global__ void add_kernel(const float* __restrict__ a, const float* __restrict__ b,
                           float* __restrict__ c, int n) {
    int i = blockIdx.x * blockDim.x + threadIdx.x;
    if (i < n) c[i] = a[i] + b[i];
}

__global__ void silu_mul_kernel(const float* __restrict__ g, const float* __restrict__ u,
                                float* __restrict__ o, int n) {
    int i = blockIdx.x * blockDim.x + threadIdx.x;
    if (i < n) {
        float x = g[i];
        o[i] = x / (1.0f + __expf(-x)) * u[i];
    }
}

// ------------------------- host orchestration -------------------------
extern "C" void kernel_launch(void* const* d_in, const int* in_sizes, int n_in,
                              void* d_out, int out_size) {
    const float* x     = (const float*)d_in[0];
    const int*   amask = (const int*)d_in[1];
    const float* wq = (const float*)d_in[2];   const float* aq_a = (const float*)d_in[3];
    const float* wk = (const float*)d_in[4];   const float* ak_a = (const float*)d_in[5];
    const float* wv = (const float*)d_in[6];   const float* av_a = (const float*)d_in[7];
    const float* wo = (const float*)d_in[8];   const float* ao_a = (const float*)d_in[9];
    const float* wg = (const float*)d_in[10];  const float* ag_a = (const float*)d_in[11];
    const float* wu = (const float*)d_in[12];  const float* au_a = (const float*)d_in[13];
    const float* wd = (const float*)d_in[14];  const float* ad_a = (const float*)d_in[15];
    const float* n1 = (const float*)d_in[16];
    const float* n2 = (const float*)d_in[17];
    float* out = (float*)d_out;

    float *p_wq, *p_wk, *p_wv, *p_wo, *p_wg, *p_wu, *p_wd;
    float *p_sq, *p_sk, *p_sv, *p_so, *p_sg, *p_su, *p_sd;
    float *p_aq, *p_as, *p_qkv, *p_q, *p_k, *p_attno, *p_x1, *p_gate, *p_up, *p_down;
    cudaGetSymbolAddress((void**)&p_wq, g_wq);
    cudaGetSymbolAddress((void**)&p_wk, g_wk);
    cudaGetSymbolAddress((void**)&p_wv, g_wv);
    cudaGetSymbolAddress((void**)&p_wo, g_wo);
    cudaGetSymbolAddress((void**)&p_wg, g_wg);
    cudaGetSymbolAddress((void**)&p_wu, g_wu);
    cudaGetSymbolAddress((void**)&p_wd, g_wd);
    cudaGetSymbolAddress((void**)&p_sq, g_sq);
    cudaGetSymbolAddress((void**)&p_sk, g_sk);
    cudaGetSymbolAddress((void**)&p_sv, g_sv);
    cudaGetSymbolAddress((void**)&p_so, g_so);
    cudaGetSymbolAddress((void**)&p_sg, g_sg);
    cudaGetSymbolAddress((void**)&p_su, g_su);
    cudaGetSymbolAddress((void**)&p_sd, g_sd);
    cudaGetSymbolAddress((void**)&p_aq, g_aq);
    cudaGetSymbolAddress((void**)&p_as, g_as);
    cudaGetSymbolAddress((void**)&p_qkv, g_qkv);
    cudaGetSymbolAddress((void**)&p_q, g_q);
    cudaGetSymbolAddress((void**)&p_k, g_k);
    cudaGetSymbolAddress((void**)&p_attno, g_attno);
    cudaGetSymbolAddress((void**)&p_x1, g_x1);
    cudaGetSymbolAddress((void**)&p_gate, g_gate);
    cudaGetSymbolAddress((void**)&p_up, g_up);
    cudaGetSymbolAddress((void**)&p_down, g_down);

    // 1) quantize all weights
    quant_w_kernel<<<HID, 256>>>(wq, aq_a, p_wq, p_sq, HID);
    quant_w_kernel<<<HID, 256>>>(wk, ak_a, p_wk, p_sk, HID);
    quant_w_kernel<<<HID, 256>>>(wv, av_a, p_wv, p_sv, HID);
    quant_w_kernel<<<HID, 256>>>(wo, ao_a, p_wo, p_so, HID);
    quant_w_kernel<<<MLPD, 256>>>(wg, ag_a, p_wg, p_sg, HID);
    quant_w_kernel<<<MLPD, 256>>>(wu, au_a, p_wu, p_su, HID);
    quant_w_kernel<<<HID, 256>>>(wd, ad_a, p_wd, p_sd, MLPD);

    // 2) rmsnorm + quantize input
    rms_quant_kernel<<<NTOK, 256>>>(x, n1, p_aq, p_as);

    // 3) q,k,v projections
    dim3 g16(HID / 128, NTOK / 128);
    gemm_bitlin_kernel<<<g16, 256>>>(p_aq, p_wq, p_sq, p_as, p_qkv, HID, HID);
    gemm_bitlin_kernel<<<g16, 256>>>(p_aq, p_wk, p_sk, p_as, p_qkv + (size_t)NTOK * HID, HID, HID);
    gemm_bitlin_kernel<<<g16, 256>>>(p_aq, p_wv, p_sv, p_as, p_qkv + 2 * (size_t)NTOK * HID, HID, HID);

    // 4) rope + transpose q,k
    rope_kernel<<<(NTOK * NH * 64 + 255) / 256, 256>>>(p_qkv, p_qkv + (size_t)NTOK * HID, p_q, p_k);

    // 5) attention (v read directly in [T,H*D] layout)
    attn_kernel<<<NTOK * NH / 8, 256>>>(p_q, p_k, p_qkv + 2 * (size_t)NTOK * HID, amask, p_attno);

    // 6) output projection
    act_quant_kernel<<<NTOK, 256>>>(p_attno, p_aq, p_as, HID);
    gemm_bitlin_kernel<<<g16, 256>>>(p_aq, p_wo, p_so, p_as, p_down, HID, HID);

    // 7) residual
    add_kernel<<<NTOK * HID / 256, 256>>>(x, p_down, p_x1, NTOK * HID);

    // 8) MLP
    rms_quant_kernel<<<NTOK, 256>>>(p_x1, n2, p_aq, p_as);
    dim3 g64(MLPD / 128, NTOK / 128);
    gemm_bitlin_kernel<<<g64, 256>>>(p_aq, p_wg, p_sg, p_as, p_gate, HID, MLPD);
    gemm_bitlin_kernel<<<g64, 256>>>(p_aq, p_wu, p_su, p_as, p_up, HID, MLPD);
    silu_mul_kernel<<<NTOK * MLPD / 256, 256>>>(p_gate, p_up, p_gate, NTOK * MLPD);
    act_quant_kernel<<<NTOK, 256>>>(p_gate, p_aq, p_as, MLPD);
    gemm_bitlin_kernel<<<g16, 256>>>(p_aq, p_wd, p_sd, p_as, p_down, MLPD, HID);

    // 9) final residual into d_out
    add_kernel<<<NTOK * HID / 256, 256>>>(p_x1, p_down, out, NTOK * HID);
    (void)in_sizes; (void)n_in; (void)out_size;
}

// round 3
// speedup vs baseline: 2.7136x; 2.7136x over previous
#include <cuda_runtime.h>
#include <cuda_bf16.h>
#include <cstdint>
#include <stdint.h>
#include <math.h>

#define NTOK   4096      // B*S
#define HID    2048
#define NH     16
#define HD     128
#define MLPD   8192
#define SEQL   2048

// ------------------------- persistent device scratch -------------------------
__device__ __nv_bfloat16 g_wq[HID * HID];
__device__ __nv_bfloat16 g_wk[HID * HID];
__device__ __nv_bfloat16 g_wv[HID * HID];
__device__ __nv_bfloat16 g_wo[HID * HID];
__device__ __nv_bfloat16 g_wg[MLPD * HID];
__device__ __nv_bfloat16 g_wu[MLPD * HID];
__device__ __nv_bfloat16 g_wd[HID * MLPD];
__device__ float g_sq[HID], g_sk[HID], g_sv[HID], g_so[HID];
__device__ float g_sg[MLPD], g_su[MLPD], g_sd[HID];

__device__ __nv_bfloat16 g_aq[NTOK * MLPD];   // quantized activations (bf16 ints)
__device__ float g_as[NTOK];                  // per-token activation scales
__device__ float g_qkv[3 * NTOK * HID];       // q_t, k_t, v_t in [T, H*D] layout
__device__ float g_q[NTOK * HID];             // roped q, [B,H,S,D]
__device__ float g_k[NTOK * HID];             // roped k, [B,H,S,D]
__device__ float g_attno[NTOK * HID];         // attention output, [T, H*D]
__device__ float g_x1[NTOK * HID];            // residual after attention
__device__ float g_gate[NTOK * MLPD];
__device__ float g_up[NTOK * MLPD];
__device__ float g_down[NTOK * HID];

// ------------------------- weight quantization (bf16 out) -------------------------
__global__ void quant_w_kernel(const float* __restrict__ W,
                               const float* __restrict__ alpha,
                               __nv_bfloat16* __restrict__ Wq,
                               float* __restrict__ rs, int K) {
    int o = blockIdx.x;
    const float4* row = (const float4*)(W + (size_t)o * K);
    int nv = K / 4;
    __shared__ float red[256];
    float s = 0.f;
    for (int i = threadIdx.x; i < nv; i += 256) {
        float4 v = row[i];
        s += fabsf(v.x) + fabsf(v.y) + fabsf(v.z) + fabsf(v.w);
    }
    red[threadIdx.x] = s;
    __syncthreads();
    for (int st = 128; st > 0; st >>= 1) {
        if (threadIdx.x < st) red[threadIdx.x] += red[threadIdx.x + st];
        __syncthreads();
    }
    float wsc = red[0] / (float)K + 1e-8f;
    if (threadIdx.x == 0) rs[o] = wsc * alpha[o] / 127.0f;
    __nv_bfloat162* orow = (__nv_bfloat162*)(Wq + (size_t)o * K);
    for (int i = threadIdx.x; i < nv; i += 256) {
        float4 v = row[i];
        float q0 = fminf(fmaxf(rintf(v.x / wsc), -1.f), 1.f);
        float q1 = fminf(fmaxf(rintf(v.y / wsc), -1.f), 1.f);
        float q2 = fminf(fmaxf(rintf(v.z / wsc), -1.f), 1.f);
        float q3 = fminf(fmaxf(rintf(v.w / wsc), -1.f), 1.f);
        orow[i * 2 + 0] = __floats2bfloat162_rn(q0, q1);
        orow[i * 2 + 1] = __floats2bfloat162_rn(q2, q3);
    }
}

// ------------------------- rmsnorm + activation quant (N = 2048, bf16 out) -------------------------
__global__ void rms_quant_kernel(const float* __restrict__ x,
                                 const float* __restrict__ w,
                                 __nv_bfloat16* __restrict__ aq,
                                 float* __restrict__ as_) {
    int t = blockIdx.x;
    const float* row = x + (size_t)t * HID;
    float v[8], h[8];
    float ss = 0.f;
#pragma unroll
    for (int j = 0; j < 8; j++) {
        v[j] = row[j * 256 + threadIdx.x];
        ss += v[j] * v[j];
    }
    __shared__ float red[256];
    red[threadIdx.x] = ss;
    __syncthreads();
    for (int st = 128; st > 0; st >>= 1) {
        if (threadIdx.x < st) red[threadIdx.x] += red[threadIdx.x + st];
        __syncthreads();
    }
    float rms = sqrtf(red[0] / (float)HID + 1e-6f);
    __syncthreads();
    float mx = 0.f;
#pragma unroll
    for (int j = 0; j < 8; j++) {
        h[j] = v[j] / rms * w[j * 256 + threadIdx.x];
        mx = fmaxf(mx, fabsf(h[j]));
    }
    red[threadIdx.x] = mx;
    __syncthreads();
    for (int st = 128; st > 0; st >>= 1) {
        if (threadIdx.x < st) red[threadIdx.x] = fmaxf(red[threadIdx.x], red[threadIdx.x + st]);
        __syncthreads();
    }
    float asc = red[0] + 1e-8f;
    if (threadIdx.x == 0) as_[t] = asc;
    __nv_bfloat16* orow = aq + (size_t)t * HID;
#pragma unroll
    for (int j = 0; j < 8; j++) {
        float q = h[j] / asc * 127.0f;
        q = fminf(fmaxf(q, -128.f), 127.f);
        orow[j * 256 + threadIdx.x] = __float2bfloat16(rintf(q));
    }
}

// ------------------------- plain activation quant (generic N, bf16 out) -------------------------
__global__ void act_quant_kernel(const float* __restrict__ x,
                                 __nv_bfloat16* __restrict__ aq,
                                 float* __restrict__ as_, int N) {
    int t = blockIdx.x;
    const float* row = x + (size_t)t * N;
    __shared__ float red[256];
    float mx = 0.f;
    for (int i = threadIdx.x; i < N; i += 256) mx = fmaxf(mx, fabsf(row[i]));
    red[threadIdx.x] = mx;
    __syncthreads();
    for (int st = 128; st > 0; st >>= 1) {
        if (threadIdx.x < st) red[threadIdx.x] = fmaxf(red[threadIdx.x], red[threadIdx.x + st]);
        __syncthreads();
    }
    float asc = red[0] + 1e-8f;
    if (threadIdx.x == 0) as_[t] = asc;
    __nv_bfloat16* orow = aq + (size_t)t * N;
    for (int i = threadIdx.x; i < N; i += 256) {
        float q = row[i] / asc * 127.0f;
        q = fminf(fmaxf(q, -128.f), 127.f);
        orow[i] = __float2bfloat16(rintf(q));
    }
}

// ------------------------- bf16 tensor-core GEMM -------------------------
// C[t,o] = (sum_k A[t,k]*W[o,k]) * rs[o] * as[t]; A:[M,K] bf16, W:[N,K] bf16.
// 128x128x64 tile, 256 threads (8 warps as 4x2), mma.sync m16n8k16 bf16.
#define BM 128
#define BN 128
#define BK 64

__device__ __forceinline__ unsigned smem_addr(const void* p) {
    return (unsigned)__cvta_generic_to_shared(p);
}
__device__ __forceinline__ void cp_async16(void* dst, const void* src) {
    asm volatile("cp.async.cg.shared.global [%0], [%1], 16;\n"
                 :: "r"(smem_addr(dst)), "l"(src));
}
__device__ __forceinline__ void cp_commit() { asm volatile("cp.async.commit_group;\n"); }
__device__ __forceinline__ void ldm4(unsigned* r, unsigned addr) {
    asm volatile("ldmatrix.sync.aligned.m8n8.x4.shared.b16 {%0,%1,%2,%3}, [%4];\n"
                 : "=r"(r[0]), "=r"(r[1]), "=r"(r[2]), "=r"(r[3]) : "r"(addr));
}
__device__ __forceinline__ void mma16816(float* c, const unsigned* a, unsigned b0, unsigned b1) {
    asm volatile(
        "mma.sync.aligned.m16n8k16.row.col.f32.bf16.bf16.f32 "
        "{%0,%1,%2,%3},{%4,%5,%6,%7},{%8,%9},{%0,%1,%2,%3};\n"
        : "+f"(c[0]), "+f"(c[1]), "+f"(c[2]), "+f"(c[3])
        : "r"(a[0]), "r"(a[1]), "r"(a[2]), "r"(a[3]), "r"(b0), "r"(b1));
}
// swizzled bf16 offset inside a [rows][BK] tile (BK=64: 8 units of 16B per row)
__device__ __forceinline__ int sw_off(int row, int u) {
    return (row * 8 + (u ^ (row & 7))) * 8;
}

__global__ void __launch_bounds__(256)
gemm_bf16_kernel(const __nv_bfloat16* __restrict__ A, const __nv_bfloat16* __restrict__ B,
                 const float* __restrict__ rs, const float* __restrict__ asc,
                 float* __restrict__ C, int K, int N) {
    extern __shared__ __nv_bfloat16 sm[];
    __nv_bfloat16* As = sm;                 // 2 * BM * BK
    __nv_bfloat16* Bs = sm + 2 * BM * BK;   // 2 * BN * BK

    const int tid = threadIdx.x;
    const int lane = tid & 31;
    const int wid = tid >> 5;
    const int warp_m = wid >> 1;            // 0..3
    const int warp_n = wid & 1;             // 0..1
    const int rowBase = blockIdx.y * BM;
    const int colBase = blockIdx.x * BN;

    float acc[2][8][4];
#pragma unroll
    for (int mt = 0; mt < 2; mt++)
#pragma unroll
        for (int nt = 0; nt < 8; nt++)
#pragma unroll
            for (int i = 0; i < 4; i++) acc[mt][nt][i] = 0.f;

    const int nsteps = K / BK;
    // prefetch tile 0
    {
        __nv_bfloat16* Ab = As;
        __nv_bfloat16* Bb = Bs;
#pragma unroll
        for (int it = 0; it < 4; it++) {
            int j = tid + it * 256;          // 0..1023
            int row = j >> 3, u = j & 7;
            cp_async16(Ab + sw_off(row, u), A + (size_t)(rowBase + row) * K + u * 8);
            cp_async16(Bb + sw_off(row, u), B + (size_t)(colBase + row) * K + u * 8);
        }
        cp_commit();
    }

    for (int s = 0; s < nsteps; s++) {
        if (s + 1 < nsteps) {
            __nv_bfloat16* Ab = As + ((s + 1) & 1) * BM * BK;
            __nv_bfloat16* Bb = Bs + ((s + 1) & 1) * BN * BK;
            int k0 = (s + 1) * BK;
#pragma unroll
            for (int it = 0; it < 4; it++) {
                int j = tid + it * 256;
                int row = j >> 3, u = j & 7;
                cp_async16(Ab + sw_off(row, u), A + (size_t)(rowBase + row) * K + k0 + u * 8);
                cp_async16(Bb + sw_off(row, u), B + (size_t)(colBase + row) * K + k0 + u * 8);
            }
            cp_commit();
            asm volatile("cp.async.wait_group 1;\n");
        } else {
            asm volatile("cp.async.wait_group 0;\n");
        }
        __syncthreads();

        const __nv_bfloat16* Ab = As + (s & 1) * BM * BK;
        const __nv_bfloat16* Bb = Bs + (s & 1) * BN * BK;
        const unsigned a_base = smem_addr(Ab);
        const unsigned b_base = smem_addr(Bb);

#pragma unroll
        for (int kc = 0; kc < 4; kc++) {
            const int u = kc * 2 + (lane >> 4);
            unsigned afrag[2][4];
#pragma unroll
            for (int mt = 0; mt < 2; mt++) {
                int row = warp_m * 32 + mt * 16 + (lane & 15);
                ldm4(afrag[mt], a_base + (unsigned)sw_off(row, u) * 2);
            }
            unsigned bfrag[8][2];
#pragma unroll
            for (int np = 0; np < 4; np++) {
                int row = warp_n * 64 + np * 16 + (lane & 15);
                unsigned r[4];
                ldm4(r, b_base + (unsigned)sw_off(row, u) * 2);
                bfrag[np * 2 + 0][0] = r[0]; bfrag[np * 2 + 0][1] = r[2];
                bfrag[np * 2 + 1][0] = r[1]; bfrag[np * 2 + 1][1] = r[3];
            }
#pragma unroll
            for (int mt = 0; mt < 2; mt++)
#pragma unroll
                for (int nt = 0; nt < 8; nt++)
                    mma16816(acc[mt][nt], afrag[mt], bfrag[nt][0], bfrag[nt][1]);
        }
        __syncthreads();
    }

    // epilogue with scales
#pragma unroll
    for (int mt = 0; mt < 2; mt++) {
        int r0 = rowBase + warp_m * 32 + mt * 16 + (lane >> 2);
        float sA = asc[r0], sB = asc[r0 + 8];
#pragma unroll
        for (int nt = 0; nt < 8; nt++) {
            int c0 = colBase + warp_n * 64 + nt * 8 + (lane & 3) * 2;
            float rs0 = rs[c0], rs1 = rs[c0 + 1];
            C[(size_t)r0 * N + c0]           = acc[mt][nt][0] * rs0 * sA;
            C[(size_t)r0 * N + c0 + 1]       = acc[mt][nt][1] * rs1 * sA;
            C[(size_t)(r0 + 8) * N + c0]     = acc[mt][nt][2] * rs0 * sB;
            C[(size_t)(r0 + 8) * N + c0 + 1] = acc[mt][nt][3] * rs1 * sB;
        }
    }
}

// ------------------------- RoPE + [T,H*D] -> [B,H,S,D] transpose for q,k -------------------------
__global__ void rope_kernel(const float* __restrict__ qt, const float* __restrict__ kt,
                            float* __restrict__ qo, float* __restrict__ ko) {
    int idx = blockIdx.x * blockDim.x + threadIdx.x;
    if (idx >= NTOK * NH * 64) return;
    int d = idx & 63;
    int th = idx >> 6;
    int h = th & (NH - 1);
    int t = th >> 4;
    int s = t & (SEQL - 1);
    int b = t >> 11;
    float invf = 1.0f / powf(10000.0f, (float)d / 64.0f);
    float ang = (float)s * invf;
    float sn, c;
    sincosf(ang, &sn, &c);
    size_t in0 = (size_t)t * HID + h * HD + d;
    size_t ob = ((size_t)(b * NH + h) * SEQL + s) * (size_t)HD + d;
    float x1 = qt[in0], x2 = qt[in0 + 64];
    qo[ob] = x1 * c - x2 * sn;
    qo[ob + 64] = x2 * c + x1 * sn;
    float y1 = kt[in0], y2 = kt[in0 + 64];
    ko[ob] = y1 * c - y2 * sn;
    ko[ob + 64] = y2 * c + y1 * sn;
}

// ------------------------- fused causal attention -------------------------
__global__ void __launch_bounds__(256)
attn_kernel(const float* __restrict__ q, const float* __restrict__ k,
            const float* __restrict__ vt, const int* __restrict__ mask,
            float* __restrict__ out) {
    __shared__ float Ks[32 * HD];
    __shared__ float Vs[32 * HD];
    const int wid = threadIdx.x >> 5;
    const int lane = threadIdx.x & 31;
    const int R = blockIdx.x * 8;
    const int s_base = R & (SEQL - 1);
    const int bh = R >> 11;
    const int h = bh & (NH - 1);
    const int b = bh >> 4;
    const int s = s_base + wid;

    const float* qrow = q + ((size_t)bh * SEQL + s) * HD;
    float q0 = qrow[lane], q1 = qrow[lane + 32], q2 = qrow[lane + 64], q3 = qrow[lane + 96];
    const float* kb = k + (size_t)bh * SEQL * HD;
    const float* vb = vt + (size_t)b * SEQL * HID + (size_t)h * HD;
    const int* mrow = mask + b * SEQL;

    float m = -1e30f, l = 0.f, a0 = 0.f, a1 = 0.f, a2 = 0.f, a3 = 0.f;
    const float scale = 0.08838834764831845f;
    const int jmax = s_base + 8;

    for (int j0 = 0; j0 < jmax; j0 += 32) {
        __syncthreads();
        int nk = min(32, jmax - j0);
        for (int i = threadIdx.x; i < nk * HD; i += 256) {
            Ks[i] = kb[(size_t)j0 * HD + i];
            int kj = i >> 7, d = i & 127;
            Vs[i] = vb[(size_t)(j0 + kj) * HID + d];
        }
        __syncthreads();
        int jend = min(nk, s - j0 + 1);
        for (int jj = 0; jj < jend; jj++) {
            const float* kr = Ks + jj * HD;
            float dot = q0 * kr[lane] + q1 * kr[lane + 32] + q2 * kr[lane + 64] + q3 * kr[lane + 96];
            dot += __shfl_xor_sync(0xffffffffu, dot, 16);
            dot += __shfl_xor_sync(0xffffffffu, dot, 8);
            dot += __shfl_xor_sync(0xffffffffu, dot, 4);
            dot += __shfl_xor_sync(0xffffffffu, dot, 2);
            dot += __shfl_xor_sync(0xffffffffu, dot, 1);
            float sc = dot * scale;
            sc = (mrow[j0 + jj] == 0) ? -10000.f : fmaxf(sc, -10000.f);
            float nm = fmaxf(m, sc);
            float cor = __expf(m - nm);
            float p = __expf(sc - nm);
            l = l * cor + p;
            const float* vr = Vs + jj * HD;
            a0 = a0 * cor + p * vr[lane];
            a1 = a1 * cor + p * vr[lane + 32];
            a2 = a2 * cor + p * vr[lane + 64];
            a3 = a3 * cor + p * vr[lane + 96];
            m = nm;
        }
    }
    float inv = 1.f / l;
    size_t ob = ((size_t)b * SEQL + s) * HID + (size_t)h * HD;
    out[ob + lane] = a0 * inv;
    out[ob + lane + 32] = a1 * inv;
    out[ob + lane + 64] = a2 * inv;
    out[ob + lane + 96] = a3 * inv;
}

// ------------------------- elementwise -------------------------
__global__ void add_kernel(const float* __restrict__ a, const float* __restrict__ b,
                           float* __restrict__ c, int n) {
    int i = blockIdx.x * blockDim.x + threadIdx.x;
    if (i < n) c[i] = a[i] + b[i];
}

__global__ void silu_mul_kernel(const float* __restrict__ g, const float* __restrict__ u,
                                float* __restrict__ o, int n) {
    int i = blockIdx.x * blockDim.x + threadIdx.x;
    if (i < n) {
        float x = g[i];
        o[i] = x / (1.0f + __expf(-x)) * u[i];
    }
}

// ------------------------- host orchestration -------------------------
extern "C" void kernel_launch(void* const* d_in, const int* in_sizes, int n_in,
                              void* d_out, int out_size) {
    const float* x     = (const float*)d_in[0];
    const int*   amask = (const int*)d_in[1];
    const float* wq = (const float*)d_in[2];   const float* aq_a = (const float*)d_in[3];
    const float* wk = (const float*)d_in[4];   const float* ak_a = (const float*)d_in[5];
    const float* wv = (const float*)d_in[6];   const float* av_a = (const float*)d_in[7];
    const float* wo = (const float*)d_in[8];   const float* ao_a = (const float*)d_in[9];
    const float* wg = (const float*)d_in[10];  const float* ag_a = (const float*)d_in[11];
    const float* wu = (const float*)d_in[12];  const float* au_a = (const float*)d_in[13];
    const float* wd = (const float*)d_in[14];  const float* ad_a = (const float*)d_in[15];
    const float* n1 = (const float*)d_in[16];
    const float* n2 = (const float*)d_in[17];
    float* out = (float*)d_out;

    __nv_bfloat16 *p_wq, *p_wk, *p_wv, *p_wo, *p_wg, *p_wu, *p_wd, *p_aq;
    float *p_sq, *p_sk, *p_sv, *p_so, *p_sg, *p_su, *p_sd;
    float *p_as, *p_qkv, *p_q, *p_k, *p_attno, *p_x1, *p_gate, *p_up, *p_down;
    cudaGetSymbolAddress((void**)&p_wq, g_wq);
    cudaGetSymbolAddress((void**)&p_wk, g_wk);
    cudaGetSymbolAddress((void**)&p_wv, g_wv);
    cudaGetSymbolAddress((void**)&p_wo, g_wo);
    cudaGetSymbolAddress((void**)&p_wg, g_wg);
    cudaGetSymbolAddress((void**)&p_wu, g_wu);
    cudaGetSymbolAddress((void**)&p_wd, g_wd);
    cudaGetSymbolAddress((void**)&p_sq, g_sq);
    cudaGetSymbolAddress((void**)&p_sk, g_sk);
    cudaGetSymbolAddress((void**)&p_sv, g_sv);
    cudaGetSymbolAddress((void**)&p_so, g_so);
    cudaGetSymbolAddress((void**)&p_sg, g_sg);
    cudaGetSymbolAddress((void**)&p_su, g_su);
    cudaGetSymbolAddress((void**)&p_sd, g_sd);
    cudaGetSymbolAddress((void**)&p_aq, g_aq);
    cudaGetSymbolAddress((void**)&p_as, g_as);
    cudaGetSymbolAddress((void**)&p_qkv, g_qkv);
    cudaGetSymbolAddress((void**)&p_q, g_q);
    cudaGetSymbolAddress((void**)&p_k, g_k);
    cudaGetSymbolAddress((void**)&p_attno, g_attno);
    cudaGetSymbolAddress((void**)&p_x1, g_x1);
    cudaGetSymbolAddress((void**)&p_gate, g_gate);
    cudaGetSymbolAddress((void**)&p_up, g_up);
    cudaGetSymbolAddress((void**)&p_down, g_down);

    const int smem_bytes = 2 * (BM * BK + BN * BK) * 2;   // 65536
    cudaFuncSetAttribute(gemm_bf16_kernel, cudaFuncAttributeMaxDynamicSharedMemorySize, smem_bytes);

    // 1) quantize all weights (bf16)
    quant_w_kernel<<<HID, 256>>>(wq, aq_a, p_wq, p_sq, HID);
    quant_w_kernel<<<HID, 256>>>(wk, ak_a, p_wk, p_sk, HID);
    quant_w_kernel<<<HID, 256>>>(wv, av_a, p_wv, p_sv, HID);
    quant_w_kernel<<<HID, 256>>>(wo, ao_a, p_wo, p_so, HID);
    quant_w_kernel<<<MLPD, 256>>>(wg, ag_a, p_wg, p_sg, HID);
    quant_w_kernel<<<MLPD, 256>>>(wu, au_a, p_wu, p_su, HID);
    quant_w_kernel<<<HID, 256>>>(wd, ad_a, p_wd, p_sd, MLPD);

    // 2) rmsnorm + quantize input
    rms_quant_kernel<<<NTOK, 256>>>(x, n1, p_aq, p_as);

    // 3) q,k,v projections
    dim3 g16(HID / BN, NTOK / BM);
    gemm_bf16_kernel<<<g16, 256, smem_bytes>>>(p_aq, p_wq, p_sq, p_as, p_qkv, HID, HID);
    gemm_bf16_kernel<<<g16, 256, smem_bytes>>>(p_aq, p_wk, p_sk, p_as, p_qkv + (size_t)NTOK * HID, HID, HID);
    gemm_bf16_kernel<<<g16, 256, smem_bytes>>>(p_aq, p_wv, p_sv, p_as, p_qkv + 2 * (size_t)NTOK * HID, HID, HID);

    // 4) rope + transpose q,k
    rope_kernel<<<(NTOK * NH * 64 + 255) / 256, 256>>>(p_qkv, p_qkv + (size_t)NTOK * HID, p_q, p_k);

    // 5) attention
    attn_kernel<<<NTOK * NH / 8, 256>>>(p_q, p_k, p_qkv + 2 * (size_t)NTOK * HID, amask, p_attno);

    // 6) output projection
    act_quant_kernel<<<NTOK, 256>>>(p_attno, p_aq, p_as, HID);
    gemm_bf16_kernel<<<g16, 256, smem_bytes>>>(p_aq, p_wo, p_so, p_as, p_down, HID, HID);

    // 7) residual
    add_kernel<<<NTOK * HID / 256, 256>>>(x, p_down, p_x1, NTOK * HID);

    // 8) MLP
    rms_quant_kernel<<<NTOK, 256>>>(p_x1, n2, p_aq, p_as);
    dim3 g64(MLPD / BN, NTOK / BM);
    gemm_bf16_kernel<<<g64, 256, smem_bytes>>>(p_aq, p_wg, p_sg, p_as, p_gate, HID, MLPD);
    gemm_bf16_kernel<<<g64, 256, smem_bytes>>>(p_aq, p_wu, p_su, p_as, p_up, HID, MLPD);
    silu_mul_kernel<<<NTOK * MLPD / 256, 256>>>(p_gate, p_up, p_gate, NTOK * MLPD);
    act_quant_kernel<<<NTOK, 256>>>(p_gate, p_aq, p_as, MLPD);
    gemm_bf16_kernel<<<g16, 256, smem_bytes>>>(p_aq, p_wd, p_sd, p_as, p_down, MLPD, HID);

    // 9) final residual into d_out
    add_kernel<<<NTOK * HID / 256, 256>>>(p_x1, p_down, out, NTOK * HID);
    (void)in_sizes; (void)n_in; (void)out_size;
}